// round 1
// baseline (speedup 1.0000x reference)
#include <cuda_runtime.h>
#include <cuda_bf16.h>

// ---------------------------------------------------------------------------
// RPN head, fp32 SIMT baseline (round 0).
//   conv1: 3x3 512->256 + bias + relu   (implicit GEMM, M=65536, N=256, K=4608)
//   conv2: 3x3 256->256 + bias + relu   (K=2304)
//   heads: 1x1 256->36 (reg) and 256->18 (cls) + pairwise softmax, interleaved out
// Scratch via __device__ globals (no allocation).
// ---------------------------------------------------------------------------

#define HDIM 128
#define WDIM 128
#define BATCH 4
#define COUT 256

__device__ float g_h1[BATCH * HDIM * WDIM * COUT];   // 64 MiB
__device__ float g_h2[BATCH * HDIM * WDIM * COUT];   // 64 MiB

// ---------------------------------------------------------------------------
// Implicit-GEMM 3x3 SAME conv + bias + relu.
// C[m][n], m = (b,y,x) with x fastest; block tile = (one full image row of 128
// positions) x (128 output channels). K = 9*CIN ordered (tap, ci).
// ---------------------------------------------------------------------------
template <int CIN>
__global__ __launch_bounds__(256, 2)
void conv3x3_relu_kernel(const float* __restrict__ in,
                         const float* __restrict__ wgt,   // [9*CIN][256] (HWIO flat)
                         const float* __restrict__ bias,  // [256]
                         float* __restrict__ out)
{
    constexpr int BM = 128, BN = 128, BK = 16;
    constexpr int KTOT = 9 * CIN;
    constexpr int NK = KTOT / BK;

    __shared__ float As[2][BK][BM];
    __shared__ float Bs[2][BK][BN];

    const int tid = threadIdx.x;
    const int bn0 = blockIdx.x * BN;        // 0 or 128
    const int my  = blockIdx.y;             // b*128 + y
    const int b   = my >> 7;
    const int y   = my & 127;

    const int tx = tid & 15;                // 0..15  -> channel microtile
    const int ty = tid >> 4;                // 0..15  -> spatial microtile

    // A-tile load mapping: 2 threads per spatial position, each loads 8
    // contiguous input channels (two float4) -> fully coalesced.
    const int ai  = tid >> 1;               // spatial x within row (0..127)
    const int akq = tid & 1;                // which 8-wide half of the 16 ci's

    // B-tile load mapping: 32 threads per K-row, float4 over channels.
    const int bkr = tid >> 5;               // 0..7
    const int bn4 = (tid & 31) * 4;         // 0..124

    float acc[8][8];
#pragma unroll
    for (int i = 0; i < 8; i++)
#pragma unroll
        for (int j = 0; j < 8; j++) acc[i][j] = 0.0f;

    float4 a0r, a1r, b0r, b1r;

    auto load_gmem = [&](int kc) {
        const int k0  = kc * BK;
        const int t   = k0 / CIN;            // tap 0..8 (BK divides CIN)
        const int ci0 = k0 - t * CIN;
        const int ky  = t / 3;
        const int kx  = t - ky * 3;
        const int yin = y + ky - 1;
        const int xin = ai + kx - 1;
        const bool valid = ((unsigned)yin < (unsigned)HDIM) &&
                           ((unsigned)xin < (unsigned)WDIM);
        if (valid) {
            const float* p = in +
                ((size_t)((b * HDIM + yin) * WDIM + xin) * CIN + ci0 + akq * 8);
            a0r = *(const float4*)(p);
            a1r = *(const float4*)(p + 4);
        } else {
            a0r = make_float4(0.f, 0.f, 0.f, 0.f);
            a1r = a0r;
        }
        const float* wq = wgt + ((size_t)(k0 + bkr) * COUT + bn0 + bn4);
        b0r = *(const float4*)(wq);
        b1r = *(const float4*)(wq + 8 * COUT);
    };

    auto store_smem = [&](int buf) {
        const int kb = akq * 8;
        As[buf][kb + 0][ai] = a0r.x;  As[buf][kb + 1][ai] = a0r.y;
        As[buf][kb + 2][ai] = a0r.z;  As[buf][kb + 3][ai] = a0r.w;
        As[buf][kb + 4][ai] = a1r.x;  As[buf][kb + 5][ai] = a1r.y;
        As[buf][kb + 6][ai] = a1r.z;  As[buf][kb + 7][ai] = a1r.w;
        *(float4*)&Bs[buf][bkr][bn4]     = b0r;
        *(float4*)&Bs[buf][bkr + 8][bn4] = b1r;
    };

    load_gmem(0);
    store_smem(0);
    __syncthreads();

    int cur = 0;
    for (int kc = 0; kc < NK; ++kc) {
        if (kc + 1 < NK) load_gmem(kc + 1);

#pragma unroll
        for (int kk = 0; kk < BK; ++kk) {
            float4 a0 = *(const float4*)&As[cur][kk][ty * 4];
            float4 a1 = *(const float4*)&As[cur][kk][64 + ty * 4];
            float4 b0 = *(const float4*)&Bs[cur][kk][tx * 4];
            float4 b1 = *(const float4*)&Bs[cur][kk][64 + tx * 4];
            float av[8] = {a0.x, a0.y, a0.z, a0.w, a1.x, a1.y, a1.z, a1.w};
            float bv[8] = {b0.x, b0.y, b0.z, b0.w, b1.x, b1.y, b1.z, b1.w};
#pragma unroll
            for (int i = 0; i < 8; i++)
#pragma unroll
                for (int j = 0; j < 8; j++)
                    acc[i][j] = fmaf(av[i], bv[j], acc[i][j]);
        }

        if (kc + 1 < NK) store_smem(cur ^ 1);
        __syncthreads();
        cur ^= 1;
    }

    // Epilogue: bias + relu + store (float4 over channels)
    float bv0[4], bv1[4];
#pragma unroll
    for (int j = 0; j < 4; j++) {
        bv0[j] = bias[bn0 + tx * 4 + j];
        bv1[j] = bias[bn0 + 64 + tx * 4 + j];
    }
    const size_t rowbase = (size_t)my * WDIM;   // (b*128+y)*128
#pragma unroll
    for (int i = 0; i < 8; i++) {
        const int xi = (i < 4) ? (ty * 4 + i) : (64 + ty * 4 + (i - 4));
        float* op = out + (rowbase + xi) * COUT + bn0;
        float4 v0, v1;
        v0.x = fmaxf(acc[i][0] + bv0[0], 0.f);
        v0.y = fmaxf(acc[i][1] + bv0[1], 0.f);
        v0.z = fmaxf(acc[i][2] + bv0[2], 0.f);
        v0.w = fmaxf(acc[i][3] + bv0[3], 0.f);
        v1.x = fmaxf(acc[i][4] + bv1[0], 0.f);
        v1.y = fmaxf(acc[i][5] + bv1[1], 0.f);
        v1.z = fmaxf(acc[i][6] + bv1[2], 0.f);
        v1.w = fmaxf(acc[i][7] + bv1[3], 0.f);
        *(float4*)(op + tx * 4)      = v0;
        *(float4*)(op + 64 + tx * 4) = v1;
    }
}

// ---------------------------------------------------------------------------
// Heads: per (position, anchor) thread. Weights staged in smem as
// ws[ci][a*6 + {c0,c1,r0,r1,r2,r3}]. Softmax over the cls pair, interleaved
// write: out[m][a][0:2]=softmax(cls), out[m][a][2:6]=reg.
// ---------------------------------------------------------------------------
__global__ __launch_bounds__(256)
void heads_kernel(const float* __restrict__ h,
                  const float* __restrict__ Wr, const float* __restrict__ br,
                  const float* __restrict__ Wc, const float* __restrict__ bc,
                  float* __restrict__ out)
{
    extern __shared__ float smem[];
    float* ws = smem;            // 256*54 floats
    float* bs = smem + 256 * 54; // 54 floats

    const int tid = threadIdx.x;

    // Stage weights: one ci per thread.
    {
        const int ci = tid;
        float* w = ws + ci * 54;
        const float* wc = Wc + ci * 18;
        const float* wr = Wr + ci * 36;
#pragma unroll
        for (int a = 0; a < 9; a++) {
            w[a * 6 + 0] = wc[2 * a + 0];
            w[a * 6 + 1] = wc[2 * a + 1];
            w[a * 6 + 2] = wr[4 * a + 0];
            w[a * 6 + 3] = wr[4 * a + 1];
            w[a * 6 + 4] = wr[4 * a + 2];
            w[a * 6 + 5] = wr[4 * a + 3];
        }
    }
    if (tid < 54) {
        const int a = tid / 6, j = tid - a * 6;
        bs[tid] = (j < 2) ? bc[2 * a + j] : br[4 * a + (j - 2)];
    }
    __syncthreads();

    const int idx = blockIdx.x * 256 + tid;      // < 65536*9, grid exact
    const int m = idx / 9;
    const int a = idx - m * 9;

    const float* hr = h + (size_t)m * 256;
    const float* wp = ws + a * 6;

    float c0 = bs[a * 6 + 0], c1 = bs[a * 6 + 1];
    float r0 = bs[a * 6 + 2], r1 = bs[a * 6 + 3];
    float r2 = bs[a * 6 + 4], r3 = bs[a * 6 + 5];

#pragma unroll 8
    for (int ci = 0; ci < 256; ci++) {
        const float hv = hr[ci];
        const float* w = wp + ci * 54;
        float2 wcv = *(const float2*)(w + 0);
        float2 wr0 = *(const float2*)(w + 2);
        float2 wr1 = *(const float2*)(w + 4);
        c0 = fmaf(hv, wcv.x, c0);
        c1 = fmaf(hv, wcv.y, c1);
        r0 = fmaf(hv, wr0.x, r0);
        r1 = fmaf(hv, wr0.y, r1);
        r2 = fmaf(hv, wr1.x, r2);
        r3 = fmaf(hv, wr1.y, r3);
    }

    const float mx = fmaxf(c0, c1);
    const float e0 = __expf(c0 - mx);
    const float e1 = __expf(c1 - mx);
    const float inv = 1.0f / (e0 + e1);

    float* op = out + (size_t)idx * 6;
    *(float2*)(op + 0) = make_float2(e0 * inv, e1 * inv);
    *(float2*)(op + 2) = make_float2(r0, r1);
    *(float2*)(op + 4) = make_float2(r2, r3);
}

// ---------------------------------------------------------------------------
extern "C" void kernel_launch(void* const* d_in, const int* in_sizes, int n_in,
                              void* d_out, int out_size)
{
    const float* x  = (const float*)d_in[0];
    const float* W1 = (const float*)d_in[1];
    const float* b1 = (const float*)d_in[2];
    const float* W2 = (const float*)d_in[3];
    const float* b2 = (const float*)d_in[4];
    const float* Wr = (const float*)d_in[5];
    const float* br = (const float*)d_in[6];
    const float* Wc = (const float*)d_in[7];
    const float* bc = (const float*)d_in[8];
    float* out = (float*)d_out;

    float *h1p = nullptr, *h2p = nullptr;
    cudaGetSymbolAddress((void**)&h1p, g_h1);
    cudaGetSymbolAddress((void**)&h2p, g_h2);

    dim3 cgrid(2, BATCH * HDIM);   // (N tiles, M tiles = b*128+y)
    conv3x3_relu_kernel<512><<<cgrid, 256>>>(x,  W1, b1, h1p);
    conv3x3_relu_kernel<256><<<cgrid, 256>>>(h1p, W2, b2, h2p);

    const int smem_heads = (256 * 54 + 64) * sizeof(float);
    cudaFuncSetAttribute(heads_kernel,
                         cudaFuncAttributeMaxDynamicSharedMemorySize, smem_heads);
    heads_kernel<<<(BATCH * HDIM * WDIM * 9) / 256, 256, smem_heads>>>(
        h2p, Wr, br, Wc, bc, out);
}

// round 3
// speedup vs baseline: 5.0548x; 5.0548x over previous
#include <cuda_runtime.h>
#include <cuda_fp16.h>
#include <cstdint>

// ---------------------------------------------------------------------------
// RPN head via mma.sync f16 (legacy tensor path; tcgen05 unavailable because
// the harness compiles with a non-'a' PTX virtual arch).
//   prep : x -> fp16; W1/W2 -> transposed fp16 [n][k]
//   conv1: 3x3 512->256 + bias + relu  (implicit GEMM, fp16 in/out, fp32 acc)
//   conv2: 3x3 256->256 + bias + relu  (fp16 in, fp32 out)
//   heads: 1x1 reg/cls + pairwise softmax (fp32 SIMT)
// ---------------------------------------------------------------------------

#define HDIM 128
#define WDIM 128
#define BATCH 4
#define COUT 256

__device__ __half g_x16[BATCH * HDIM * WDIM * 512];   // 64 MiB
__device__ __half g_h1 [BATCH * HDIM * WDIM * COUT];  // 32 MiB
__device__ float  g_h2 [BATCH * HDIM * WDIM * COUT];  // 64 MiB
__device__ __half g_w1t[COUT * 9 * 512];
__device__ __half g_w2t[COUT * 9 * 256];

// ---------------- mma.sync / ldmatrix / cp.async helpers -------------------

__device__ __forceinline__ void ldsm4(uint32_t* r, uint32_t addr) {
    asm volatile("ldmatrix.sync.aligned.m8n8.x4.shared.b16 {%0,%1,%2,%3}, [%4];"
                 : "=r"(r[0]), "=r"(r[1]), "=r"(r[2]), "=r"(r[3]) : "r"(addr));
}

__device__ __forceinline__ void mma16816(float* d, const uint32_t* a,
                                         const uint32_t* b) {
    asm volatile(
        "mma.sync.aligned.m16n8k16.row.col.f32.f16.f16.f32 "
        "{%0,%1,%2,%3}, {%4,%5,%6,%7}, {%8,%9}, {%0,%1,%2,%3};"
        : "+f"(d[0]), "+f"(d[1]), "+f"(d[2]), "+f"(d[3])
        : "r"(a[0]), "r"(a[1]), "r"(a[2]), "r"(a[3]), "r"(b[0]), "r"(b[1]));
}

__device__ __forceinline__ void cp_async16(uint32_t dst, const void* src,
                                           uint32_t nbytes) {
    asm volatile("cp.async.cg.shared.global [%0], [%1], 16, %2;"
                 :: "r"(dst), "l"(src), "r"(nbytes));
}
#define CP_COMMIT() asm volatile("cp.async.commit_group;")
#define CP_WAIT2()  asm volatile("cp.async.wait_group 2;")
#define CP_WAIT0()  asm volatile("cp.async.wait_group 0;")

// ---------------------------------------------------------------------------
// Prep kernels
// ---------------------------------------------------------------------------
__global__ void cvt_x_kernel(const float* __restrict__ x,
                             __half* __restrict__ o, int n8)
{
    const int i = blockIdx.x * 256 + threadIdx.x;
    if (i < n8) {
        const float4* p = (const float4*)x + (size_t)i * 2;
        const float4 a = p[0], bq = p[1];
        __half2 h[4];
        h[0] = __floats2half2_rn(a.x, a.y);
        h[1] = __floats2half2_rn(a.z, a.w);
        h[2] = __floats2half2_rn(bq.x, bq.y);
        h[3] = __floats2half2_rn(bq.z, bq.w);
        *(uint4*)(o + (size_t)i * 8) = *(uint4*)h;
    }
}

__global__ void wtrans_kernel(const float* __restrict__ w,
                              __half* __restrict__ wt, int K)
{
    const int idx = blockIdx.x * 256 + threadIdx.x;
    if (idx < K * 256) {
        const int k = idx >> 8;
        const int n = idx & 255;
        wt[(size_t)n * K + k] = __float2half(w[idx]);
    }
}

// ---------------------------------------------------------------------------
// Implicit-GEMM 3x3 SAME conv + bias + relu on mma.sync f16.
// M = b*H*W positions (BM=128 = one image row), N = 256 (BN=128), K = 9*CIN.
// Smem: 16B units, unit(m,h) = m*4 + (h ^ ((m>>1)&3)) -> conflict-free for
// both cp.async 16B stores and ldmatrix row fetches. 4-stage cp.async pipe.
// ---------------------------------------------------------------------------
template <int CIN, typename OutT>
__global__ __launch_bounds__(256)
void conv_mma(const __half* __restrict__ in, const __half* __restrict__ wt,
              const float* __restrict__ bias, OutT* __restrict__ out)
{
    constexpr int KTOT = 9 * CIN;
    constexpr int BK = 32;
    constexpr int NS = KTOT / BK;
    constexpr int STGB = 16384;            // A 8KB + B 8KB per stage

    extern __shared__ char smem[];
    const uint32_t sb = (uint32_t)__cvta_generic_to_shared(smem);
    float* bias_s = (float*)(smem + 4 * STGB);

    const int tid = threadIdx.x;
    const int lid = tid & 31;
    const int wid = tid >> 5;
    const int wm = wid & 1;                // 2 M-warp groups (64 rows each)
    const int wn = wid >> 1;               // 4 N-warp groups (32 cols each)

    const int nt = blockIdx.x;             // 0..1 : N tile
    const int bm = blockIdx.y;             // 0..511 : (b*128 + y)
    const int b  = bm >> 7;
    const int y  = bm & 127;
    const int bn0 = nt * 128;
    const __half* inb = in + (size_t)b * HDIM * WDIM * CIN;

    if (tid < 128) bias_s[tid] = bias[bn0 + tid];

    const int sh = tid & 3;                // staging: k-half within BK (16B)
    const int sm = tid >> 2;               // staging: row 0..63

    auto issue = [&](int s) {
        const int buf = s & 3;
        const int k0  = s * BK;
        const int tap = k0 / CIN;
        const int ci0 = k0 - tap * CIN;
        const int ky  = tap / 3;
        const int kx  = tap - 3 * ky;
        const int yin = y + ky - 1;
        const bool yok = (unsigned)yin < (unsigned)HDIM;
        const uint32_t ab  = sb + (uint32_t)buf * STGB;
        const uint32_t bb2 = ab + 8192;
#pragma unroll
        for (int i = 0; i < 2; ++i) {
            const int m = sm + 64 * i;
            const int xin = m + kx - 1;
            const bool ok = yok && ((unsigned)xin < (unsigned)WDIM);
            const __half* src = ok
                ? inb + ((size_t)(yin * WDIM + xin) * CIN + ci0 + sh * 8)
                : inb;
            const uint32_t unit = m * 4 + (sh ^ ((m >> 1) & 3));
            cp_async16(ab + unit * 16, src, ok ? 16u : 0u);
        }
#pragma unroll
        for (int i = 0; i < 2; ++i) {
            const int n = sm + 64 * i;
            const __half* src = wt + (size_t)(bn0 + n) * KTOT + k0 + sh * 8;
            const uint32_t unit = n * 4 + (sh ^ ((n >> 1) & 3));
            cp_async16(bb2 + unit * 16, src, 16u);
        }
    };

    float acc[4][4][4];
#pragma unroll
    for (int i = 0; i < 4; ++i)
#pragma unroll
        for (int j = 0; j < 4; ++j)
#pragma unroll
            for (int k = 0; k < 4; ++k) acc[i][j][k] = 0.0f;

    issue(0); CP_COMMIT();
    issue(1); CP_COMMIT();
    issue(2); CP_COMMIT();

    const int q = lid >> 3;                // matrix index group
    const int r = lid & 7;                 // row within matrix

    for (int s = 0; s < NS; ++s) {
        CP_WAIT2();
        __syncthreads();
        if (s + 3 < NS) issue(s + 3);
        CP_COMMIT();

        const uint32_t ab  = sb + (uint32_t)(s & 3) * STGB;
        const uint32_t bb2 = ab + 8192;
#pragma unroll
        for (int c = 0; c < 2; ++c) {      // two k16 chunks per BK=32
            uint32_t af[4][4];
#pragma unroll
            for (int i = 0; i < 4; ++i) {
                const int m = wm * 64 + i * 16 + (q & 1) * 8 + r;
                const int h = 2 * c + (q >> 1);
                const uint32_t unit = m * 4 + (h ^ ((m >> 1) & 3));
                ldsm4(af[i], ab + unit * 16);
            }
            uint32_t bf[2][4];
#pragma unroll
            for (int p = 0; p < 2; ++p) {
                const int n = wn * 32 + p * 16 + (q >> 1) * 8 + r;
                const int h = 2 * c + (q & 1);
                const uint32_t unit = n * 4 + (h ^ ((n >> 1) & 3));
                ldsm4(bf[p], bb2 + unit * 16);
            }
#pragma unroll
            for (int i = 0; i < 4; ++i)
#pragma unroll
                for (int j = 0; j < 4; ++j)
                    mma16816(acc[i][j], af[i], &bf[j >> 1][(j & 1) * 2]);
        }
        __syncthreads();
    }

    // -------- epilogue: bias + relu + store --------
    const int g  = lid >> 2;
    const int t4 = lid & 3;
    const size_t posb = (size_t)bm * 128;
#pragma unroll
    for (int i = 0; i < 4; ++i) {
#pragma unroll
        for (int row = 0; row < 2; ++row) {
            const int m = wm * 64 + i * 16 + row * 8 + g;
            OutT* op = out + (posb + m) * COUT + bn0;
#pragma unroll
            for (int j = 0; j < 4; ++j) {
                const int n = wn * 32 + j * 8 + 2 * t4;
                const float v0 = fmaxf(acc[i][j][row * 2 + 0] + bias_s[n], 0.f);
                const float v1 = fmaxf(acc[i][j][row * 2 + 1] + bias_s[n + 1], 0.f);
                if constexpr (sizeof(OutT) == 2) {
                    *(__half2*)((__half*)op + n) = __floats2half2_rn(v0, v1);
                } else {
                    *(float2*)((float*)op + n) = make_float2(v0, v1);
                }
            }
        }
    }
    CP_WAIT0();
}

// ---------------------------------------------------------------------------
// Heads: per (position, anchor) thread; smem-staged interleaved weights,
// fused pairwise softmax. fp32.
// ---------------------------------------------------------------------------
__global__ __launch_bounds__(256)
void heads_kernel(const float* __restrict__ h,
                  const float* __restrict__ Wr, const float* __restrict__ br,
                  const float* __restrict__ Wc, const float* __restrict__ bc,
                  float* __restrict__ out)
{
    extern __shared__ float hsm[];
    float* ws = hsm;
    float* bs = hsm + 256 * 54;

    const int tid = threadIdx.x;
    {
        const int ci = tid;
        float* w = ws + ci * 54;
        const float* wc = Wc + ci * 18;
        const float* wr = Wr + ci * 36;
#pragma unroll
        for (int a = 0; a < 9; a++) {
            w[a * 6 + 0] = wc[2 * a + 0];
            w[a * 6 + 1] = wc[2 * a + 1];
            w[a * 6 + 2] = wr[4 * a + 0];
            w[a * 6 + 3] = wr[4 * a + 1];
            w[a * 6 + 4] = wr[4 * a + 2];
            w[a * 6 + 5] = wr[4 * a + 3];
        }
    }
    if (tid < 54) {
        const int a = tid / 6, j = tid - a * 6;
        bs[tid] = (j < 2) ? bc[2 * a + j] : br[4 * a + (j - 2)];
    }
    __syncthreads();

    const int idx = blockIdx.x * 256 + tid;
    const int m = idx / 9;
    const int a = idx - m * 9;

    const float* hr = h + (size_t)m * 256;
    const float* wp = ws + a * 6;

    float c0 = bs[a * 6 + 0], c1 = bs[a * 6 + 1];
    float r0 = bs[a * 6 + 2], r1 = bs[a * 6 + 3];
    float r2 = bs[a * 6 + 4], r3 = bs[a * 6 + 5];

#pragma unroll 8
    for (int ci = 0; ci < 256; ci++) {
        const float hv = hr[ci];
        const float* w = wp + ci * 54;
        float2 wcv = *(const float2*)(w + 0);
        float2 wr0 = *(const float2*)(w + 2);
        float2 wr1 = *(const float2*)(w + 4);
        c0 = fmaf(hv, wcv.x, c0);
        c1 = fmaf(hv, wcv.y, c1);
        r0 = fmaf(hv, wr0.x, r0);
        r1 = fmaf(hv, wr0.y, r1);
        r2 = fmaf(hv, wr1.x, r2);
        r3 = fmaf(hv, wr1.y, r3);
    }

    const float mx = fmaxf(c0, c1);
    const float e0 = __expf(c0 - mx);
    const float e1 = __expf(c1 - mx);
    const float inv = 1.0f / (e0 + e1);

    float* op = out + (size_t)idx * 6;
    *(float2*)(op + 0) = make_float2(e0 * inv, e1 * inv);
    *(float2*)(op + 2) = make_float2(r0, r1);
    *(float2*)(op + 4) = make_float2(r2, r3);
}

// ---------------------------------------------------------------------------
extern "C" void kernel_launch(void* const* d_in, const int* in_sizes, int n_in,
                              void* d_out, int out_size)
{
    const float* x  = (const float*)d_in[0];
    const float* W1 = (const float*)d_in[1];
    const float* b1 = (const float*)d_in[2];
    const float* W2 = (const float*)d_in[3];
    const float* b2 = (const float*)d_in[4];
    const float* Wr = (const float*)d_in[5];
    const float* br = (const float*)d_in[6];
    const float* Wc = (const float*)d_in[7];
    const float* bc = (const float*)d_in[8];
    float* out = (float*)d_out;

    __half *x16p, *h1p, *w1tp, *w2tp;
    float *h2p;
    cudaGetSymbolAddress((void**)&x16p, g_x16);
    cudaGetSymbolAddress((void**)&h1p,  g_h1);
    cudaGetSymbolAddress((void**)&h2p,  g_h2);
    cudaGetSymbolAddress((void**)&w1tp, g_w1t);
    cudaGetSymbolAddress((void**)&w2tp, g_w2t);

    // prep
    const int n8 = BATCH * HDIM * WDIM * 512 / 8;
    cvt_x_kernel<<<(n8 + 255) / 256, 256>>>(x, x16p, n8);
    wtrans_kernel<<<(9 * 512 * 256 + 255) / 256, 256>>>(W1, w1tp, 9 * 512);
    wtrans_kernel<<<(9 * 256 * 256 + 255) / 256, 256>>>(W2, w2tp, 9 * 256);

    const int conv_smem = 4 * 16384 + 512;   // 66048 B
    cudaFuncSetAttribute(conv_mma<512, __half>,
                         cudaFuncAttributeMaxDynamicSharedMemorySize, conv_smem);
    cudaFuncSetAttribute(conv_mma<256, float>,
                         cudaFuncAttributeMaxDynamicSharedMemorySize, conv_smem);

    conv_mma<512, __half><<<dim3(2, 512), 256, conv_smem>>>(x16p, w1tp, b1, h1p);
    conv_mma<256, float ><<<dim3(2, 512), 256, conv_smem>>>(h1p,  w2tp, b2, h2p);

    const int smem_heads = (256 * 54 + 64) * sizeof(float);
    cudaFuncSetAttribute(heads_kernel,
                         cudaFuncAttributeMaxDynamicSharedMemorySize, smem_heads);
    heads_kernel<<<(BATCH * HDIM * WDIM * 9) / 256, 256, smem_heads>>>(
        h2p, Wr, br, Wc, bc, out);
}

// round 4
// speedup vs baseline: 7.3400x; 1.4521x over previous
#include <cuda_runtime.h>
#include <cuda_fp16.h>
#include <cstdint>

// ---------------------------------------------------------------------------
// RPN head via mma.sync f16 (tcgen05 blocked: harness PTX arch lacks 'a').
//   prep : x -> fp16; W1/W2 -> transposed fp16 [n][k]; head weights -> [64][256]
//   conv1: 3x3 512->256 + bias + relu   (fp16 in/out, fp32 acc)
//   conv2: 3x3 256->256 + bias + relu   (fp16 in/out)
//   heads: GEMM M=65536 N=64(54) K=256 + bias + pairwise softmax epilogue
// ---------------------------------------------------------------------------

#define HDIM 128
#define WDIM 128
#define BATCH 4
#define COUT 256

__device__ __half g_x16[BATCH * HDIM * WDIM * 512];   // 64 MiB
__device__ __half g_h1 [BATCH * HDIM * WDIM * COUT];  // 32 MiB
__device__ __half g_h2 [BATCH * HDIM * WDIM * COUT];  // 32 MiB
__device__ __half g_w1t[COUT * 9 * 512];
__device__ __half g_w2t[COUT * 9 * 256];
__device__ __half g_wh [64 * 256];                    // head weights, padded
__device__ float  g_bh [64];                          // head bias, padded

// ---------------- mma.sync / ldmatrix / cp.async helpers -------------------

__device__ __forceinline__ void ldsm4(uint32_t* r, uint32_t addr) {
    asm volatile("ldmatrix.sync.aligned.m8n8.x4.shared.b16 {%0,%1,%2,%3}, [%4];"
                 : "=r"(r[0]), "=r"(r[1]), "=r"(r[2]), "=r"(r[3]) : "r"(addr));
}

__device__ __forceinline__ void mma16816(float* d, const uint32_t* a,
                                         const uint32_t* b) {
    asm volatile(
        "mma.sync.aligned.m16n8k16.row.col.f32.f16.f16.f32 "
        "{%0,%1,%2,%3}, {%4,%5,%6,%7}, {%8,%9}, {%0,%1,%2,%3};"
        : "+f"(d[0]), "+f"(d[1]), "+f"(d[2]), "+f"(d[3])
        : "r"(a[0]), "r"(a[1]), "r"(a[2]), "r"(a[3]), "r"(b[0]), "r"(b[1]));
}

__device__ __forceinline__ void cp_async16(uint32_t dst, const void* src,
                                           uint32_t nbytes) {
    asm volatile("cp.async.cg.shared.global [%0], [%1], 16, %2;"
                 :: "r"(dst), "l"(src), "r"(nbytes));
}
#define CP_COMMIT() asm volatile("cp.async.commit_group;")
#define CP_WAIT2()  asm volatile("cp.async.wait_group 2;")
#define CP_WAIT0()  asm volatile("cp.async.wait_group 0;")

// ---------------------------------------------------------------------------
// Prep kernels
// ---------------------------------------------------------------------------
__global__ void cvt_x_kernel(const float* __restrict__ x,
                             __half* __restrict__ o, int n8)
{
    const int i = blockIdx.x * 256 + threadIdx.x;
    if (i < n8) {
        const float4* p = (const float4*)x + (size_t)i * 2;
        const float4 a = p[0], bq = p[1];
        __half2 h[4];
        h[0] = __floats2half2_rn(a.x, a.y);
        h[1] = __floats2half2_rn(a.z, a.w);
        h[2] = __floats2half2_rn(bq.x, bq.y);
        h[3] = __floats2half2_rn(bq.z, bq.w);
        *(uint4*)(o + (size_t)i * 8) = *(uint4*)h;
    }
}

__global__ void wtrans_kernel(const float* __restrict__ w,
                              __half* __restrict__ wt, int K)
{
    const int idx = blockIdx.x * 256 + threadIdx.x;
    if (idx < K * 256) {
        const int k = idx >> 8;
        const int n = idx & 255;
        wt[(size_t)n * K + k] = __float2half(w[idx]);
    }
}

// Head weights: Wh[n][ci], n = a*6 + j, j<2 -> cls, else reg; n>=54 -> 0.
__global__ void whead_kernel(const float* __restrict__ Wr,
                             const float* __restrict__ br,
                             const float* __restrict__ Wc,
                             const float* __restrict__ bc,
                             __half* __restrict__ wh, float* __restrict__ bh)
{
    const int idx = blockIdx.x * 256 + threadIdx.x;   // 64*256
    const int n  = idx & 63;
    const int ci = idx >> 6;
    float v = 0.f;
    if (n < 54) {
        const int a = n / 6, j = n - 6 * a;
        v = (j < 2) ? Wc[ci * 18 + 2 * a + j] : Wr[ci * 36 + 4 * a + (j - 2)];
    }
    wh[(size_t)n * 256 + ci] = __float2half(v);
    if (ci == 0) {
        float bb = 0.f;
        if (n < 54) {
            const int a = n / 6, j = n - 6 * a;
            bb = (j < 2) ? bc[2 * a + j] : br[4 * a + (j - 2)];
        }
        bh[n] = bb;
    }
}

// ---------------------------------------------------------------------------
// Implicit-GEMM 3x3 SAME conv + bias + relu on mma.sync f16.
// BM=128 (one image row), BN=128, BK=32, 4-stage cp.async, 8 warps.
// One barrier per stage; all 12 LDSM batched ahead of 32 MMAs; stage loop
// unrolled x4 so smem addresses constant-fold.
// ---------------------------------------------------------------------------
template <int CIN>
__global__ __launch_bounds__(256, 2)
void conv_mma(const __half* __restrict__ in, const __half* __restrict__ wt,
              const float* __restrict__ bias, __half* __restrict__ out)
{
    constexpr int KTOT = 9 * CIN;
    constexpr int BK = 32;
    constexpr int NS = KTOT / BK;          // 144 or 72 (divisible by 4)
    constexpr int STGB = 16384;

    extern __shared__ char smem[];
    const uint32_t sb = (uint32_t)__cvta_generic_to_shared(smem);
    float* bias_s = (float*)(smem + 4 * STGB);

    const int tid = threadIdx.x;
    const int lid = tid & 31;
    const int wid = tid >> 5;
    const int wm = wid & 1;
    const int wn = wid >> 1;

    const int nt = blockIdx.x;
    const int bm = blockIdx.y;             // b*128 + y
    const int b  = bm >> 7;
    const int y  = bm & 127;
    const int bn0 = nt * 128;
    const __half* inb = in + (size_t)b * HDIM * WDIM * CIN;

    if (tid < 128) bias_s[tid] = bias[bn0 + tid];

    const int sh = tid & 3;
    const int sm = tid >> 2;

    auto issue = [&](int s, int buf) {
        const int k0  = s * BK;
        const int tap = k0 / CIN;
        const int ci0 = k0 - tap * CIN;
        const int ky  = tap / 3;
        const int kx  = tap - 3 * ky;
        const int yin = y + ky - 1;
        const bool yok = (unsigned)yin < (unsigned)HDIM;
        const uint32_t ab  = sb + (uint32_t)buf * STGB;
        const uint32_t bb2 = ab + 8192;
#pragma unroll
        for (int i = 0; i < 2; ++i) {
            const int m = sm + 64 * i;
            const int xin = m + kx - 1;
            const bool ok = yok && ((unsigned)xin < (unsigned)WDIM);
            const __half* src = ok
                ? inb + ((size_t)(yin * WDIM + xin) * CIN + ci0 + sh * 8)
                : inb;
            const uint32_t unit = m * 4 + (sh ^ ((m >> 1) & 3));
            cp_async16(ab + unit * 16, src, ok ? 16u : 0u);
        }
#pragma unroll
        for (int i = 0; i < 2; ++i) {
            const int n = sm + 64 * i;
            const __half* src = wt + (size_t)(bn0 + n) * KTOT + k0 + sh * 8;
            const uint32_t unit = n * 4 + (sh ^ ((n >> 1) & 3));
            cp_async16(bb2 + unit * 16, src, 16u);
        }
    };

    const int q = lid >> 3;
    const int r = lid & 7;

    // Precompute per-warp swizzled LDSM byte offsets (loop-invariant).
    uint32_t offA[2][4], offB[2][2];
#pragma unroll
    for (int c = 0; c < 2; ++c) {
#pragma unroll
        for (int i = 0; i < 4; ++i) {
            const int m = wm * 64 + i * 16 + (q & 1) * 8 + r;
            const int h = 2 * c + (q >> 1);
            offA[c][i] = (m * 4 + (h ^ ((m >> 1) & 3))) * 16;
        }
#pragma unroll
        for (int p = 0; p < 2; ++p) {
            const int n = wn * 32 + p * 16 + (q >> 1) * 8 + r;
            const int h = 2 * c + (q & 1);
            offB[c][p] = (n * 4 + (h ^ ((n >> 1) & 3))) * 16 + 8192;
        }
    }

    float acc[4][4][4];
#pragma unroll
    for (int i = 0; i < 4; ++i)
#pragma unroll
        for (int j = 0; j < 4; ++j)
#pragma unroll
            for (int k = 0; k < 4; ++k) acc[i][j][k] = 0.0f;

    issue(0, 0); CP_COMMIT();
    issue(1, 1); CP_COMMIT();
    issue(2, 2); CP_COMMIT();

    for (int s4 = 0; s4 < NS; s4 += 4) {
#pragma unroll
        for (int u = 0; u < 4; ++u) {
            const int s = s4 + u;
            CP_WAIT2();
            __syncthreads();
            const uint32_t ab = sb + (uint32_t)u * STGB;

            uint32_t af[2][4][4], bf[2][2][4];
#pragma unroll
            for (int c = 0; c < 2; ++c) {
#pragma unroll
                for (int i = 0; i < 4; ++i) ldsm4(af[c][i], ab + offA[c][i]);
#pragma unroll
                for (int p = 0; p < 2; ++p) ldsm4(bf[c][p], ab + offB[c][p]);
            }

            if (s + 3 < NS) issue(s + 3, (u + 3) & 3);
            CP_COMMIT();

#pragma unroll
            for (int c = 0; c < 2; ++c)
#pragma unroll
                for (int i = 0; i < 4; ++i)
#pragma unroll
                    for (int j = 0; j < 4; ++j)
                        mma16816(acc[i][j], af[c][i], &bf[c][j >> 1][(j & 1) * 2]);
        }
    }

    // -------- epilogue: bias + relu + fp16 store --------
    const int g  = lid >> 2;
    const int t4 = lid & 3;
    const size_t posb = (size_t)bm * 128;
#pragma unroll
    for (int i = 0; i < 4; ++i) {
#pragma unroll
        for (int row = 0; row < 2; ++row) {
            const int m = wm * 64 + i * 16 + row * 8 + g;
            __half* op = out + (posb + m) * COUT + bn0;
#pragma unroll
            for (int j = 0; j < 4; ++j) {
                const int n = wn * 32 + j * 8 + 2 * t4;
                const float v0 = fmaxf(acc[i][j][row * 2 + 0] + bias_s[n], 0.f);
                const float v1 = fmaxf(acc[i][j][row * 2 + 1] + bias_s[n + 1], 0.f);
                *(__half2*)(op + n) = __floats2half2_rn(v0, v1);
            }
        }
    }
    CP_WAIT0();
}

// ---------------------------------------------------------------------------
// Heads GEMM: D[65536, 64] = h2[65536, 256] @ Wh[64, 256]^T, fused bias +
// pairwise softmax epilogue. BM=128, BN=64, BK=32, 4-stage pipeline, 8 warps
// (warp tile 32x32). Output col n0 = a*6 + rem maps flat: out[pos*54 + n0].
// ---------------------------------------------------------------------------
__global__ __launch_bounds__(256, 2)
void heads_gemm(const __half* __restrict__ h, const __half* __restrict__ wh,
                const float* __restrict__ bh, float* __restrict__ out)
{
    constexpr int NS = 8;                   // K=256 / BK=32
    constexpr int STGB = 12288;             // A 8KB + B 4KB

    extern __shared__ char smem[];
    const uint32_t sb = (uint32_t)__cvta_generic_to_shared(smem);
    float* bias_s = (float*)(smem + 4 * STGB);

    const int tid = threadIdx.x;
    const int lid = tid & 31;
    const int wid = tid >> 5;
    const int wm = wid & 3;                 // 4 M groups of 32
    const int wn = wid >> 2;                // 2 N groups of 32

    const size_t posb = (size_t)blockIdx.x * 128;
    if (tid < 64) bias_s[tid] = bh[tid];

    const int sh = tid & 3;
    const int sm = tid >> 2;

    auto issue = [&](int s, int buf) {
        const int k0 = s * 32;
        const uint32_t ab  = sb + (uint32_t)buf * STGB;
        const uint32_t bb2 = ab + 8192;
#pragma unroll
        for (int i = 0; i < 2; ++i) {
            const int m = sm + 64 * i;
            const __half* src = h + (posb + m) * 256 + k0 + sh * 8;
            const uint32_t unit = m * 4 + (sh ^ ((m >> 1) & 3));
            cp_async16(ab + unit * 16, src, 16u);
        }
        {
            const int n = sm;               // 0..63
            const __half* src = wh + (size_t)n * 256 + k0 + sh * 8;
            const uint32_t unit = n * 4 + (sh ^ ((n >> 1) & 3));
            cp_async16(bb2 + unit * 16, src, 16u);
        }
    };

    const int q = lid >> 3;
    const int r = lid & 7;

    uint32_t offA[2][2], offB[2][2];
#pragma unroll
    for (int c = 0; c < 2; ++c) {
#pragma unroll
        for (int i = 0; i < 2; ++i) {
            const int m = wm * 32 + i * 16 + (q & 1) * 8 + r;
            const int hh = 2 * c + (q >> 1);
            offA[c][i] = (m * 4 + (hh ^ ((m >> 1) & 3))) * 16;
        }
#pragma unroll
        for (int p = 0; p < 2; ++p) {
            const int n = wn * 32 + p * 16 + (q >> 1) * 8 + r;
            const int hh = 2 * c + (q & 1);
            offB[c][p] = (n * 4 + (hh ^ ((n >> 1) & 3))) * 16 + 8192;
        }
    }

    float acc[2][4][4];
#pragma unroll
    for (int i = 0; i < 2; ++i)
#pragma unroll
        for (int j = 0; j < 4; ++j)
#pragma unroll
            for (int k = 0; k < 4; ++k) acc[i][j][k] = 0.0f;

    issue(0, 0); CP_COMMIT();
    issue(1, 1); CP_COMMIT();
    issue(2, 2); CP_COMMIT();

#pragma unroll
    for (int s = 0; s < NS; ++s) {
        CP_WAIT2();
        __syncthreads();
        const uint32_t ab = sb + (uint32_t)(s & 3) * STGB;

        uint32_t af[2][2][4], bf[2][2][4];
#pragma unroll
        for (int c = 0; c < 2; ++c) {
#pragma unroll
            for (int i = 0; i < 2; ++i) ldsm4(af[c][i], ab + offA[c][i]);
#pragma unroll
            for (int p = 0; p < 2; ++p) ldsm4(bf[c][p], ab + offB[c][p]);
        }

        if (s + 3 < NS) issue(s + 3, (s + 3) & 3);
        CP_COMMIT();

#pragma unroll
        for (int c = 0; c < 2; ++c)
#pragma unroll
            for (int i = 0; i < 2; ++i)
#pragma unroll
                for (int j = 0; j < 4; ++j)
                    mma16816(acc[i][j], af[c][i], &bf[c][j >> 1][(j & 1) * 2]);
    }

    // -------- epilogue: bias + pairwise softmax + store --------
    const int g  = lid >> 2;
    const int t4 = lid & 3;
#pragma unroll
    for (int i = 0; i < 2; ++i) {
#pragma unroll
        for (int row = 0; row < 2; ++row) {
            const int m = wm * 32 + i * 16 + row * 8 + g;
            float* op = out + (posb + m) * 54;
#pragma unroll
            for (int j = 0; j < 4; ++j) {
                const int n0 = wn * 32 + j * 8 + 2 * t4;
                if (n0 < 54) {
                    float v0 = acc[i][j][row * 2 + 0] + bias_s[n0];
                    float v1 = acc[i][j][row * 2 + 1] + bias_s[n0 + 1];
                    const int a   = n0 / 6;
                    const int rem = n0 - 6 * a;
                    if (rem == 0) {          // cls pair -> softmax
                        const float mx = fmaxf(v0, v1);
                        const float e0 = __expf(v0 - mx);
                        const float e1 = __expf(v1 - mx);
                        const float inv = 1.0f / (e0 + e1);
                        v0 = e0 * inv;
                        v1 = e1 * inv;
                    }
                    *(float2*)(op + n0) = make_float2(v0, v1);
                }
            }
        }
    }
    CP_WAIT0();
}

// ---------------------------------------------------------------------------
extern "C" void kernel_launch(void* const* d_in, const int* in_sizes, int n_in,
                              void* d_out, int out_size)
{
    const float* x  = (const float*)d_in[0];
    const float* W1 = (const float*)d_in[1];
    const float* b1 = (const float*)d_in[2];
    const float* W2 = (const float*)d_in[3];
    const float* b2 = (const float*)d_in[4];
    const float* Wr = (const float*)d_in[5];
    const float* br = (const float*)d_in[6];
    const float* Wc = (const float*)d_in[7];
    const float* bc = (const float*)d_in[8];
    float* out = (float*)d_out;

    __half *x16p, *h1p, *h2p, *w1tp, *w2tp, *whp;
    float *bhp;
    cudaGetSymbolAddress((void**)&x16p, g_x16);
    cudaGetSymbolAddress((void**)&h1p,  g_h1);
    cudaGetSymbolAddress((void**)&h2p,  g_h2);
    cudaGetSymbolAddress((void**)&w1tp, g_w1t);
    cudaGetSymbolAddress((void**)&w2tp, g_w2t);
    cudaGetSymbolAddress((void**)&whp,  g_wh);
    cudaGetSymbolAddress((void**)&bhp,  g_bh);

    // prep
    const int n8 = BATCH * HDIM * WDIM * 512 / 8;
    cvt_x_kernel<<<(n8 + 255) / 256, 256>>>(x, x16p, n8);
    wtrans_kernel<<<(9 * 512 * 256 + 255) / 256, 256>>>(W1, w1tp, 9 * 512);
    wtrans_kernel<<<(9 * 256 * 256 + 255) / 256, 256>>>(W2, w2tp, 9 * 256);
    whead_kernel<<<64, 256>>>(Wr, br, Wc, bc, whp, bhp);

    const int conv_smem = 4 * 16384 + 512;
    cudaFuncSetAttribute(conv_mma<512>,
                         cudaFuncAttributeMaxDynamicSharedMemorySize, conv_smem);
    cudaFuncSetAttribute(conv_mma<256>,
                         cudaFuncAttributeMaxDynamicSharedMemorySize, conv_smem);

    conv_mma<512><<<dim3(2, 512), 256, conv_smem>>>(x16p, w1tp, b1, h1p);
    conv_mma<256><<<dim3(2, 512), 256, conv_smem>>>(h1p,  w2tp, b2, h2p);

    const int heads_smem = 4 * 12288 + 256;
    cudaFuncSetAttribute(heads_gemm,
                         cudaFuncAttributeMaxDynamicSharedMemorySize, heads_smem);
    heads_gemm<<<512, 256, heads_smem>>>(h2p, whp, bhp, out);
}

// round 5
// speedup vs baseline: 7.9289x; 1.0802x over previous
#include <cuda_runtime.h>
#include <cuda_fp16.h>
#include <cstdint>

// ---------------------------------------------------------------------------
// RPN head via mma.sync f16 (tcgen05 blocked: harness PTX arch lacks 'a').
// R5: convs restructured to BM=64 x BN=256 tiles (halved A traffic, 4:1
// better MMA:LDSM ratio on B-side amortization, 2 CTAs/SM).
//   conv1: 3x3 512->256 + bias + relu   (fp16 in/out, fp32 acc)
//   conv2: 3x3 256->256 + bias + relu   (fp16 in/out)
//   heads: GEMM M=65536 N=64(54) K=256 + bias + pairwise softmax epilogue
// ---------------------------------------------------------------------------

#define HDIM 128
#define WDIM 128
#define BATCH 4
#define COUT 256

__device__ __half g_x16[BATCH * HDIM * WDIM * 512];   // 64 MiB
__device__ __half g_h1 [BATCH * HDIM * WDIM * COUT];  // 32 MiB
__device__ __half g_h2 [BATCH * HDIM * WDIM * COUT];  // 32 MiB
__device__ __half g_w1t[COUT * 9 * 512];
__device__ __half g_w2t[COUT * 9 * 256];
__device__ __half g_wh [64 * 256];
__device__ float  g_bh [64];

// ---------------- mma.sync / ldmatrix / cp.async helpers -------------------

__device__ __forceinline__ void ldsm4(uint32_t* r, uint32_t addr) {
    asm volatile("ldmatrix.sync.aligned.m8n8.x4.shared.b16 {%0,%1,%2,%3}, [%4];"
                 : "=r"(r[0]), "=r"(r[1]), "=r"(r[2]), "=r"(r[3]) : "r"(addr));
}

__device__ __forceinline__ void mma16816(float* d, const uint32_t* a,
                                         const uint32_t* b) {
    asm volatile(
        "mma.sync.aligned.m16n8k16.row.col.f32.f16.f16.f32 "
        "{%0,%1,%2,%3}, {%4,%5,%6,%7}, {%8,%9}, {%0,%1,%2,%3};"
        : "+f"(d[0]), "+f"(d[1]), "+f"(d[2]), "+f"(d[3])
        : "r"(a[0]), "r"(a[1]), "r"(a[2]), "r"(a[3]), "r"(b[0]), "r"(b[1]));
}

__device__ __forceinline__ void cp_async16(uint32_t dst, const void* src,
                                           uint32_t nbytes) {
    asm volatile("cp.async.cg.shared.global [%0], [%1], 16, %2;"
                 :: "r"(dst), "l"(src), "r"(nbytes));
}
#define CP_COMMIT() asm volatile("cp.async.commit_group;")
#define CP_WAIT2()  asm volatile("cp.async.wait_group 2;")
#define CP_WAIT0()  asm volatile("cp.async.wait_group 0;")

// ---------------------------------------------------------------------------
// Prep kernels
// ---------------------------------------------------------------------------
__global__ void cvt_x_kernel(const float* __restrict__ x,
                             __half* __restrict__ o, int n8)
{
    const int i = blockIdx.x * 256 + threadIdx.x;
    if (i < n8) {
        const float4* p = (const float4*)x + (size_t)i * 2;
        const float4 a = p[0], bq = p[1];
        __half2 h[4];
        h[0] = __floats2half2_rn(a.x, a.y);
        h[1] = __floats2half2_rn(a.z, a.w);
        h[2] = __floats2half2_rn(bq.x, bq.y);
        h[3] = __floats2half2_rn(bq.z, bq.w);
        *(uint4*)(o + (size_t)i * 8) = *(uint4*)h;
    }
}

__global__ void wtrans_kernel(const float* __restrict__ w,
                              __half* __restrict__ wt, int K)
{
    const int idx = blockIdx.x * 256 + threadIdx.x;
    if (idx < K * 256) {
        const int k = idx >> 8;
        const int n = idx & 255;
        wt[(size_t)n * K + k] = __float2half(w[idx]);
    }
}

__global__ void whead_kernel(const float* __restrict__ Wr,
                             const float* __restrict__ br,
                             const float* __restrict__ Wc,
                             const float* __restrict__ bc,
                             __half* __restrict__ wh, float* __restrict__ bh)
{
    const int idx = blockIdx.x * 256 + threadIdx.x;   // 64*256
    const int n  = idx & 63;
    const int ci = idx >> 6;
    float v = 0.f;
    if (n < 54) {
        const int a = n / 6, j = n - 6 * a;
        v = (j < 2) ? Wc[ci * 18 + 2 * a + j] : Wr[ci * 36 + 4 * a + (j - 2)];
    }
    wh[(size_t)n * 256 + ci] = __float2half(v);
    if (ci == 0) {
        float bb = 0.f;
        if (n < 54) {
            const int a = n / 6, j = n - 6 * a;
            bb = (j < 2) ? bc[2 * a + j] : br[4 * a + (j - 2)];
        }
        bh[n] = bb;
    }
}

// ---------------------------------------------------------------------------
// Implicit-GEMM 3x3 SAME conv + bias + relu on mma.sync f16.
// BM=64 (half image row), BN=256 (all output channels), BK=32, 4-stage
// cp.async pipeline, 8 warps (warp tile 32x64), 2 CTAs/SM.
// Smem 16B units, unit(row,h) = row*4 + (h ^ ((row>>1)&3)) — conflict-free
// for cp.async stores and ldmatrix fetches.
// ---------------------------------------------------------------------------
template <int CIN>
__global__ __launch_bounds__(256, 2)
void conv_mma(const __half* __restrict__ in, const __half* __restrict__ wt,
              const float* __restrict__ bias, __half* __restrict__ out)
{
    constexpr int KTOT = 9 * CIN;
    constexpr int BK = 32;
    constexpr int NS = KTOT / BK;          // 144 or 72 (divisible by 4)
    constexpr int STGB = 20480;            // A 4KB + B 16KB per stage

    extern __shared__ char smem[];
    const uint32_t sb = (uint32_t)__cvta_generic_to_shared(smem);
    float* bias_s = (float*)(smem + 4 * STGB);

    const int tid = threadIdx.x;
    const int lid = tid & 31;
    const int wid = tid >> 5;
    const int wm = wid & 1;                // 2 M groups of 32 rows
    const int wn = wid >> 1;               // 4 N groups of 64 cols

    const int bm = blockIdx.x >> 1;        // row index: b*128 + y
    const int x0 = (blockIdx.x & 1) * 64;  // half-row offset
    const int b  = bm >> 7;
    const int y  = bm & 127;
    const __half* inb = in + (size_t)b * HDIM * WDIM * CIN;

    bias_s[tid] = bias[tid];

    const int sh = tid & 3;                // k-half within BK (16B)
    const int sm = tid >> 2;               // row 0..63

    auto issue = [&](int s, int buf) {
        const int k0  = s * BK;
        const int tap = k0 / CIN;
        const int ci0 = k0 - tap * CIN;
        const int ky  = tap / 3;
        const int kx  = tap - 3 * ky;
        const int yin = y + ky - 1;
        const bool yok = (unsigned)yin < (unsigned)HDIM;
        const uint32_t ab  = sb + (uint32_t)buf * STGB;
        const uint32_t bb2 = ab + 4096;
        {   // A: one 16B unit per thread (64 rows x 4 halves)
            const int xin = x0 + sm + kx - 1;
            const bool ok = yok && ((unsigned)xin < (unsigned)WDIM);
            const __half* src = ok
                ? inb + ((size_t)(yin * WDIM + xin) * CIN + ci0 + sh * 8)
                : inb;
            const uint32_t unit = sm * 4 + (sh ^ ((sm >> 1) & 3));
            cp_async16(ab + unit * 16, src, ok ? 16u : 0u);
        }
#pragma unroll
        for (int i = 0; i < 4; ++i) {      // B: 256 n-rows
            const int n = sm + 64 * i;
            const __half* src = wt + (size_t)n * KTOT + k0 + sh * 8;
            const uint32_t unit = n * 4 + (sh ^ ((n >> 1) & 3));
            cp_async16(bb2 + unit * 16, src, 16u);
        }
    };

    const int q = lid >> 3;
    const int r = lid & 7;

    // Loop-invariant swizzled LDSM byte offsets.
    uint32_t offA[2][2], offB[2][4];
#pragma unroll
    for (int c = 0; c < 2; ++c) {
#pragma unroll
        for (int i = 0; i < 2; ++i) {
            const int m = wm * 32 + i * 16 + (q & 1) * 8 + r;
            const int h = 2 * c + (q >> 1);
            offA[c][i] = (m * 4 + (h ^ ((m >> 1) & 3))) * 16;
        }
#pragma unroll
        for (int p = 0; p < 4; ++p) {
            const int n = wn * 64 + p * 16 + (q >> 1) * 8 + r;
            const int h = 2 * c + (q & 1);
            offB[c][p] = (n * 4 + (h ^ ((n >> 1) & 3))) * 16 + 4096;
        }
    }

    float acc[2][8][4];
#pragma unroll
    for (int i = 0; i < 2; ++i)
#pragma unroll
        for (int j = 0; j < 8; ++j)
#pragma unroll
            for (int k = 0; k < 4; ++k) acc[i][j][k] = 0.0f;

    issue(0, 0); CP_COMMIT();
    issue(1, 1); CP_COMMIT();
    issue(2, 2); CP_COMMIT();

    for (int s4 = 0; s4 < NS; s4 += 4) {
#pragma unroll
        for (int u = 0; u < 4; ++u) {
            const int s = s4 + u;
            CP_WAIT2();
            __syncthreads();
            const uint32_t ab = sb + (uint32_t)u * STGB;

            // ---- chunk c = 0 ----
            uint32_t af[2][4], bf[4][4];
#pragma unroll
            for (int i = 0; i < 2; ++i) ldsm4(af[i], ab + offA[0][i]);
#pragma unroll
            for (int p = 0; p < 4; ++p) ldsm4(bf[p], ab + offB[0][p]);

            if (s + 3 < NS) issue(s + 3, (u + 3) & 3);
            CP_COMMIT();

#pragma unroll
            for (int i = 0; i < 2; ++i)
#pragma unroll
                for (int j = 0; j < 8; ++j)
                    mma16816(acc[i][j], af[i], &bf[j >> 1][(j & 1) * 2]);

            // ---- chunk c = 1 ----
#pragma unroll
            for (int i = 0; i < 2; ++i) ldsm4(af[i], ab + offA[1][i]);
#pragma unroll
            for (int p = 0; p < 4; ++p) ldsm4(bf[p], ab + offB[1][p]);
#pragma unroll
            for (int i = 0; i < 2; ++i)
#pragma unroll
                for (int j = 0; j < 8; ++j)
                    mma16816(acc[i][j], af[i], &bf[j >> 1][(j & 1) * 2]);
        }
    }

    // -------- epilogue: bias + relu + fp16 store --------
    const int g  = lid >> 2;
    const int t4 = lid & 3;
    const size_t posb = (size_t)bm * 128 + x0;
#pragma unroll
    for (int i = 0; i < 2; ++i) {
#pragma unroll
        for (int row = 0; row < 2; ++row) {
            const int m = wm * 32 + i * 16 + row * 8 + g;
            __half* op = out + (posb + m) * COUT;
#pragma unroll
            for (int j = 0; j < 8; ++j) {
                const int n = wn * 64 + j * 8 + 2 * t4;
                const float v0 = fmaxf(acc[i][j][row * 2 + 0] + bias_s[n], 0.f);
                const float v1 = fmaxf(acc[i][j][row * 2 + 1] + bias_s[n + 1], 0.f);
                *(__half2*)(op + n) = __floats2half2_rn(v0, v1);
            }
        }
    }
    CP_WAIT0();
}

// ---------------------------------------------------------------------------
// Heads GEMM: D[65536, 64] = h2[65536, 256] @ Wh[64, 256]^T, fused bias +
// pairwise softmax epilogue. BM=128, BN=64, BK=32, 4-stage pipeline, 8 warps.
// ---------------------------------------------------------------------------
__global__ __launch_bounds__(256, 2)
void heads_gemm(const __half* __restrict__ h, const __half* __restrict__ wh,
                const float* __restrict__ bh, float* __restrict__ out)
{
    constexpr int NS = 8;
    constexpr int STGB = 12288;

    extern __shared__ char smem[];
    const uint32_t sb = (uint32_t)__cvta_generic_to_shared(smem);
    float* bias_s = (float*)(smem + 4 * STGB);

    const int tid = threadIdx.x;
    const int lid = tid & 31;
    const int wid = tid >> 5;
    const int wm = wid & 3;
    const int wn = wid >> 2;

    const size_t posb = (size_t)blockIdx.x * 128;
    if (tid < 64) bias_s[tid] = bh[tid];

    const int sh = tid & 3;
    const int sm = tid >> 2;

    auto issue = [&](int s, int buf) {
        const int k0 = s * 32;
        const uint32_t ab  = sb + (uint32_t)buf * STGB;
        const uint32_t bb2 = ab + 8192;
#pragma unroll
        for (int i = 0; i < 2; ++i) {
            const int m = sm + 64 * i;
            const __half* src = h + (posb + m) * 256 + k0 + sh * 8;
            const uint32_t unit = m * 4 + (sh ^ ((m >> 1) & 3));
            cp_async16(ab + unit * 16, src, 16u);
        }
        {
            const int n = sm;
            const __half* src = wh + (size_t)n * 256 + k0 + sh * 8;
            const uint32_t unit = n * 4 + (sh ^ ((n >> 1) & 3));
            cp_async16(bb2 + unit * 16, src, 16u);
        }
    };

    const int q = lid >> 3;
    const int r = lid & 7;

    uint32_t offA[2][2], offB[2][2];
#pragma unroll
    for (int c = 0; c < 2; ++c) {
#pragma unroll
        for (int i = 0; i < 2; ++i) {
            const int m = wm * 32 + i * 16 + (q & 1) * 8 + r;
            const int hh = 2 * c + (q >> 1);
            offA[c][i] = (m * 4 + (hh ^ ((m >> 1) & 3))) * 16;
        }
#pragma unroll
        for (int p = 0; p < 2; ++p) {
            const int n = wn * 32 + p * 16 + (q >> 1) * 8 + r;
            const int hh = 2 * c + (q & 1);
            offB[c][p] = (n * 4 + (hh ^ ((n >> 1) & 3))) * 16 + 8192;
        }
    }

    float acc[2][4][4];
#pragma unroll
    for (int i = 0; i < 2; ++i)
#pragma unroll
        for (int j = 0; j < 4; ++j)
#pragma unroll
            for (int k = 0; k < 4; ++k) acc[i][j][k] = 0.0f;

    issue(0, 0); CP_COMMIT();
    issue(1, 1); CP_COMMIT();
    issue(2, 2); CP_COMMIT();

#pragma unroll
    for (int s = 0; s < NS; ++s) {
        CP_WAIT2();
        __syncthreads();
        const uint32_t ab = sb + (uint32_t)(s & 3) * STGB;

        uint32_t af[2][2][4], bf[2][2][4];
#pragma unroll
        for (int c = 0; c < 2; ++c) {
#pragma unroll
            for (int i = 0; i < 2; ++i) ldsm4(af[c][i], ab + offA[c][i]);
#pragma unroll
            for (int p = 0; p < 2; ++p) ldsm4(bf[c][p], ab + offB[c][p]);
        }

        if (s + 3 < NS) issue(s + 3, (s + 3) & 3);
        CP_COMMIT();

#pragma unroll
        for (int c = 0; c < 2; ++c)
#pragma unroll
            for (int i = 0; i < 2; ++i)
#pragma unroll
                for (int j = 0; j < 4; ++j)
                    mma16816(acc[i][j], af[c][i], &bf[c][j >> 1][(j & 1) * 2]);
    }

    const int g  = lid >> 2;
    const int t4 = lid & 3;
#pragma unroll
    for (int i = 0; i < 2; ++i) {
#pragma unroll
        for (int row = 0; row < 2; ++row) {
            const int m = wm * 32 + i * 16 + row * 8 + g;
            float* op = out + (posb + m) * 54;
#pragma unroll
            for (int j = 0; j < 4; ++j) {
                const int n0 = wn * 32 + j * 8 + 2 * t4;
                if (n0 < 54) {
                    float v0 = acc[i][j][row * 2 + 0] + bias_s[n0];
                    float v1 = acc[i][j][row * 2 + 1] + bias_s[n0 + 1];
                    const int a   = n0 / 6;
                    const int rem = n0 - 6 * a;
                    if (rem == 0) {
                        const float mx = fmaxf(v0, v1);
                        const float e0 = __expf(v0 - mx);
                        const float e1 = __expf(v1 - mx);
                        const float inv = 1.0f / (e0 + e1);
                        v0 = e0 * inv;
                        v1 = e1 * inv;
                    }
                    *(float2*)(op + n0) = make_float2(v0, v1);
                }
            }
        }
    }
    CP_WAIT0();
}

// ---------------------------------------------------------------------------
extern "C" void kernel_launch(void* const* d_in, const int* in_sizes, int n_in,
                              void* d_out, int out_size)
{
    const float* x  = (const float*)d_in[0];
    const float* W1 = (const float*)d_in[1];
    const float* b1 = (const float*)d_in[2];
    const float* W2 = (const float*)d_in[3];
    const float* b2 = (const float*)d_in[4];
    const float* Wr = (const float*)d_in[5];
    const float* br = (const float*)d_in[6];
    const float* Wc = (const float*)d_in[7];
    const float* bc = (const float*)d_in[8];
    float* out = (float*)d_out;

    __half *x16p, *h1p, *h2p, *w1tp, *w2tp, *whp;
    float *bhp;
    cudaGetSymbolAddress((void**)&x16p, g_x16);
    cudaGetSymbolAddress((void**)&h1p,  g_h1);
    cudaGetSymbolAddress((void**)&h2p,  g_h2);
    cudaGetSymbolAddress((void**)&w1tp, g_w1t);
    cudaGetSymbolAddress((void**)&w2tp, g_w2t);
    cudaGetSymbolAddress((void**)&whp,  g_wh);
    cudaGetSymbolAddress((void**)&bhp,  g_bh);

    // prep
    const int n8 = BATCH * HDIM * WDIM * 512 / 8;
    cvt_x_kernel<<<(n8 + 255) / 256, 256>>>(x, x16p, n8);
    wtrans_kernel<<<(9 * 512 * 256 + 255) / 256, 256>>>(W1, w1tp, 9 * 512);
    wtrans_kernel<<<(9 * 256 * 256 + 255) / 256, 256>>>(W2, w2tp, 9 * 256);
    whead_kernel<<<64, 256>>>(Wr, br, Wc, bc, whp, bhp);

    const int conv_smem = 4 * 20480 + 1024;   // 82944 B
    cudaFuncSetAttribute(conv_mma<512>,
                         cudaFuncAttributeMaxDynamicSharedMemorySize, conv_smem);
    cudaFuncSetAttribute(conv_mma<256>,
                         cudaFuncAttributeMaxDynamicSharedMemorySize, conv_smem);

    conv_mma<512><<<1024, 256, conv_smem>>>(x16p, w1tp, b1, h1p);
    conv_mma<256><<<1024, 256, conv_smem>>>(h1p,  w2tp, b2, h2p);

    const int heads_smem = 4 * 12288 + 256;
    cudaFuncSetAttribute(heads_gemm,
                         cudaFuncAttributeMaxDynamicSharedMemorySize, heads_smem);
    heads_gemm<<<512, 256, heads_smem>>>(h2p, whp, bhp, out);
}

// round 7
// speedup vs baseline: 8.0474x; 1.0149x over previous
#include <cuda_runtime.h>
#include <cuda_fp16.h>
#include <cstdint>

// ---------------------------------------------------------------------------
// RPN head via mma.sync f16 (tcgen05 blocked: harness PTX arch lacks 'a').
// R7 = R6 fused design with the smem-layout bug fixed:
//   h2/Wh smem tiles: 64 rows x 256 k (fp16) -> 528-byte row stride
//   (32 data units + 1 pad unit), full-K Wh staging, extra barrier before
//   smem reuse (closes buf3 WAR race).
//   conv1: 3x3 512->256 + bias + relu   -> h1 (fp16, gmem)
//   conv2: 3x3 256->256 + bias + relu   -> smem -> fused heads GEMM
//          (M=64 N=64(54) K=256) + bias + pairwise softmax -> out
// ---------------------------------------------------------------------------

#define HDIM 128
#define WDIM 128
#define BATCH 4
#define COUT 256

__device__ __half g_x16[BATCH * HDIM * WDIM * 512];   // 64 MiB
__device__ __half g_h1 [BATCH * HDIM * WDIM * COUT];  // 32 MiB
__device__ __half g_w1t[COUT * 9 * 512];
__device__ __half g_w2t[COUT * 9 * 256];
__device__ __half g_wh [64 * 256];
__device__ float  g_bh [64];

// ---------------- mma.sync / ldmatrix / cp.async helpers -------------------

__device__ __forceinline__ void ldsm4(uint32_t* r, uint32_t addr) {
    asm volatile("ldmatrix.sync.aligned.m8n8.x4.shared.b16 {%0,%1,%2,%3}, [%4];"
                 : "=r"(r[0]), "=r"(r[1]), "=r"(r[2]), "=r"(r[3]) : "r"(addr));
}

__device__ __forceinline__ void mma16816(float* d, const uint32_t* a,
                                         const uint32_t* b) {
    asm volatile(
        "mma.sync.aligned.m16n8k16.row.col.f32.f16.f16.f32 "
        "{%0,%1,%2,%3}, {%4,%5,%6,%7}, {%8,%9}, {%0,%1,%2,%3};"
        : "+f"(d[0]), "+f"(d[1]), "+f"(d[2]), "+f"(d[3])
        : "r"(a[0]), "r"(a[1]), "r"(a[2]), "r"(a[3]), "r"(b[0]), "r"(b[1]));
}

__device__ __forceinline__ void cp_async16(uint32_t dst, const void* src,
                                           uint32_t nbytes) {
    asm volatile("cp.async.cg.shared.global [%0], [%1], 16, %2;"
                 :: "r"(dst), "l"(src), "r"(nbytes));
}
#define CP_COMMIT() asm volatile("cp.async.commit_group;")
#define CP_WAIT2()  asm volatile("cp.async.wait_group 2;")
#define CP_WAIT0()  asm volatile("cp.async.wait_group 0;")

// ---------------------------------------------------------------------------
// Prep kernels
// ---------------------------------------------------------------------------
__global__ void cvt_x_kernel(const float* __restrict__ x,
                             __half* __restrict__ o, int n8)
{
    const int i = blockIdx.x * 256 + threadIdx.x;
    if (i < n8) {
        const float4* p = (const float4*)x + (size_t)i * 2;
        const float4 a = p[0], bq = p[1];
        __half2 h[4];
        h[0] = __floats2half2_rn(a.x, a.y);
        h[1] = __floats2half2_rn(a.z, a.w);
        h[2] = __floats2half2_rn(bq.x, bq.y);
        h[3] = __floats2half2_rn(bq.z, bq.w);
        *(uint4*)(o + (size_t)i * 8) = *(uint4*)h;
    }
}

__global__ void wtrans_kernel(const float* __restrict__ w,
                              __half* __restrict__ wt, int K)
{
    const int idx = blockIdx.x * 256 + threadIdx.x;
    if (idx < K * 256) {
        const int k = idx >> 8;
        const int n = idx & 255;
        wt[(size_t)n * K + k] = __float2half(w[idx]);
    }
}

__global__ void whead_kernel(const float* __restrict__ Wr,
                             const float* __restrict__ br,
                             const float* __restrict__ Wc,
                             const float* __restrict__ bc,
                             __half* __restrict__ wh, float* __restrict__ bh)
{
    const int idx = blockIdx.x * 256 + threadIdx.x;   // 64*256
    const int n  = idx & 63;
    const int ci = idx >> 6;
    float v = 0.f;
    if (n < 54) {
        const int a = n / 6, j = n - 6 * a;
        v = (j < 2) ? Wc[ci * 18 + 2 * a + j] : Wr[ci * 36 + 4 * a + (j - 2)];
    }
    wh[(size_t)n * 256 + ci] = __float2half(v);
    if (ci == 0) {
        float bb = 0.f;
        if (n < 54) {
            const int a = n / 6, j = n - 6 * a;
            bb = (j < 2) ? bc[2 * a + j] : br[4 * a + (j - 2)];
        }
        bh[n] = bb;
    }
}

// ---------------------------------------------------------------------------
// Implicit-GEMM 3x3 SAME conv + bias + relu on mma.sync f16.
// BM=64, BN=256, BK=32, 4-stage cp.async, 8 warps (warp tile 32x64),
// 2 CTAs/SM. FUSE=true runs the heads GEMM from an smem-held h2 tile.
// ---------------------------------------------------------------------------
template <int CIN, bool FUSE>
__global__ __launch_bounds__(256, 2)
void conv_mma(const __half* __restrict__ in, const __half* __restrict__ wt,
              const float* __restrict__ bias, void* __restrict__ outv,
              const __half* __restrict__ wh, const float* __restrict__ bh)
{
    constexpr int KTOT = 9 * CIN;
    constexpr int BK = 32;
    constexpr int NS = KTOT / BK;          // 144 or 72 (divisible by 4)
    constexpr int STGB = 20480;            // A 4KB + B 16KB per stage
    constexpr int HROW = 528;              // fused tile row stride (bytes)

    extern __shared__ char smem[];
    const uint32_t sb = (uint32_t)__cvta_generic_to_shared(smem);
    float* bias_s = (float*)(smem + 4 * STGB);
    float* bh_s   = bias_s + 256;

    const int tid = threadIdx.x;
    const int lid = tid & 31;
    const int wid = tid >> 5;
    const int wm = wid & 1;                // 2 M groups of 32 rows
    const int wn = wid >> 1;               // 4 N groups of 64 cols

    const int bm = blockIdx.x >> 1;        // row index: b*128 + y
    const int x0 = (blockIdx.x & 1) * 64;  // half-row offset
    const int b  = bm >> 7;
    const int y  = bm & 127;
    const __half* inb = in + (size_t)b * HDIM * WDIM * CIN;

    bias_s[tid] = bias[tid];
    if (FUSE && tid < 64) bh_s[tid] = bh[tid];

    const int sh = tid & 3;                // k-half within BK (16B)
    const int sm = tid >> 2;               // row 0..63

    auto issue = [&](int s, int buf) {
        const int k0  = s * BK;
        const int tap = k0 / CIN;
        const int ci0 = k0 - tap * CIN;
        const int ky  = tap / 3;
        const int kx  = tap - 3 * ky;
        const int yin = y + ky - 1;
        const bool yok = (unsigned)yin < (unsigned)HDIM;
        const uint32_t ab  = sb + (uint32_t)buf * STGB;
        const uint32_t bb2 = ab + 4096;
        {   // A: one 16B unit per thread
            const int xin = x0 + sm + kx - 1;
            const bool ok = yok && ((unsigned)xin < (unsigned)WDIM);
            const __half* src = ok
                ? inb + ((size_t)(yin * WDIM + xin) * CIN + ci0 + sh * 8)
                : inb;
            const uint32_t unit = sm * 4 + (sh ^ ((sm >> 1) & 3));
            cp_async16(ab + unit * 16, src, ok ? 16u : 0u);
        }
#pragma unroll
        for (int i = 0; i < 4; ++i) {      // B: 256 n-rows
            const int n = sm + 64 * i;
            const __half* src = wt + (size_t)n * KTOT + k0 + sh * 8;
            const uint32_t unit = n * 4 + (sh ^ ((n >> 1) & 3));
            cp_async16(bb2 + unit * 16, src, 16u);
        }
    };

    const int q = lid >> 3;
    const int r = lid & 7;

    uint32_t offA[2][2], offB[2][4];
#pragma unroll
    for (int c = 0; c < 2; ++c) {
#pragma unroll
        for (int i = 0; i < 2; ++i) {
            const int m = wm * 32 + i * 16 + (q & 1) * 8 + r;
            const int h = 2 * c + (q >> 1);
            offA[c][i] = (m * 4 + (h ^ ((m >> 1) & 3))) * 16;
        }
#pragma unroll
        for (int p = 0; p < 4; ++p) {
            const int n = wn * 64 + p * 16 + (q >> 1) * 8 + r;
            const int h = 2 * c + (q & 1);
            offB[c][p] = (n * 4 + (h ^ ((n >> 1) & 3))) * 16 + 4096;
        }
    }

    float acc[2][8][4];
#pragma unroll
    for (int i = 0; i < 2; ++i)
#pragma unroll
        for (int j = 0; j < 8; ++j)
#pragma unroll
            for (int k = 0; k < 4; ++k) acc[i][j][k] = 0.0f;

    issue(0, 0); CP_COMMIT();
    issue(1, 1); CP_COMMIT();
    issue(2, 2); CP_COMMIT();

    for (int s4 = 0; s4 < NS; s4 += 4) {
#pragma unroll
        for (int u = 0; u < 4; ++u) {
            const int s = s4 + u;
            CP_WAIT2();
            __syncthreads();
            const uint32_t ab = sb + (uint32_t)u * STGB;

            uint32_t af[2][4], bf[4][4];
#pragma unroll
            for (int i = 0; i < 2; ++i) ldsm4(af[i], ab + offA[0][i]);
#pragma unroll
            for (int p = 0; p < 4; ++p) ldsm4(bf[p], ab + offB[0][p]);

            if (s + 3 < NS) issue(s + 3, (u + 3) & 3);
            CP_COMMIT();

#pragma unroll
            for (int i = 0; i < 2; ++i)
#pragma unroll
                for (int j = 0; j < 8; ++j)
                    mma16816(acc[i][j], af[i], &bf[j >> 1][(j & 1) * 2]);

#pragma unroll
            for (int i = 0; i < 2; ++i) ldsm4(af[i], ab + offA[1][i]);
#pragma unroll
            for (int p = 0; p < 4; ++p) ldsm4(bf[p], ab + offB[1][p]);
#pragma unroll
            for (int i = 0; i < 2; ++i)
#pragma unroll
                for (int j = 0; j < 8; ++j)
                    mma16816(acc[i][j], af[i], &bf[j >> 1][(j & 1) * 2]);
        }
    }

    const int g  = lid >> 2;
    const int t4 = lid & 3;
    const size_t posb = (size_t)bm * 128 + x0;

    if constexpr (!FUSE) {
        // -------- epilogue: bias + relu + fp16 store to gmem --------
        __half* out = (__half*)outv;
#pragma unroll
        for (int i = 0; i < 2; ++i) {
#pragma unroll
            for (int row = 0; row < 2; ++row) {
                const int m = wm * 32 + i * 16 + row * 8 + g;
                __half* op = out + (posb + m) * COUT;
#pragma unroll
                for (int j = 0; j < 8; ++j) {
                    const int n = wn * 64 + j * 8 + 2 * t4;
                    const float v0 = fmaxf(acc[i][j][row * 2 + 0] + bias_s[n], 0.f);
                    const float v1 = fmaxf(acc[i][j][row * 2 + 1] + bias_s[n + 1], 0.f);
                    *(__half2*)(op + n) = __floats2half2_rn(v0, v1);
                }
            }
        }
        CP_WAIT0();
    } else {
        // -------- fused heads: h2 tile -> smem, heads GEMM, softmax --------
        float* out = (float*)outv;
        // Tile layout: 64 rows x 256 k fp16 = 32 16B-units/row, row stride
        // 528 B (33 units). stride mod 128 B = 16 -> consecutive rows shift
        // one bank group; conflict-free for ldmatrix (8 rows -> 8 distinct
        // groups) and for the half2 STS pattern (bank = lid).
        const uint32_t h2b = sb;                 // overlays buf0..buf1
        const uint32_t whb = sb + 2 * STGB;      // overlays buf2..buf3

        // All buf reads (incl. buf3 stage-u=3 ldsm by slower warps) must
        // finish before any overlay writes.
        __syncthreads();

        {   // stage Wh[64][256]: 4 threads/row, 8 units each
            const int n4 = tid >> 2;
            const int h4 = tid & 3;
#pragma unroll
            for (int i = 0; i < 8; ++i) {
                const int h = h4 * 8 + i;       // unit 0..31
                cp_async16(whb + (uint32_t)(n4 * HROW + h * 16),
                           wh + (size_t)n4 * 256 + h * 8, 16u);
            }
        }
        CP_COMMIT();

        // write h2 tile (relu + bias, fp16)
#pragma unroll
        for (int i = 0; i < 2; ++i) {
#pragma unroll
            for (int row = 0; row < 2; ++row) {
                const int m = wm * 32 + i * 16 + row * 8 + g;
#pragma unroll
                for (int j = 0; j < 8; ++j) {
                    const int n = wn * 64 + j * 8 + 2 * t4;
                    const float v0 = fmaxf(acc[i][j][row * 2 + 0] + bias_s[n], 0.f);
                    const float v1 = fmaxf(acc[i][j][row * 2 + 1] + bias_s[n + 1], 0.f);
                    const __half2 hv = __floats2half2_rn(v0, v1);
                    const uint32_t addr = h2b + (uint32_t)(m * HROW + (n >> 3) * 16
                                                           + (n & 7) * 2);
                    asm volatile("st.shared.b32 [%0], %1;"
                                 :: "r"(addr), "r"(*(const uint32_t*)&hv)
                                 : "memory");
                }
            }
        }
        CP_WAIT0();
        __syncthreads();

        // heads GEMM: 64x64x256, warp tile 32(m) x 16(n)
        const int wm2 = wid & 1;
        const int wn2 = wid >> 1;
        float acc2[2][2][4];
#pragma unroll
        for (int i = 0; i < 2; ++i)
#pragma unroll
            for (int j = 0; j < 2; ++j)
#pragma unroll
                for (int k = 0; k < 4; ++k) acc2[i][j][k] = 0.0f;

        uint32_t hoffA[2], hoffB;
#pragma unroll
        for (int i = 0; i < 2; ++i) {
            const int m = wm2 * 32 + i * 16 + (q & 1) * 8 + r;
            hoffA[i] = (uint32_t)(m * HROW + (q >> 1) * 16);
        }
        {
            const int n = wn2 * 16 + (q >> 1) * 8 + r;
            hoffB = (uint32_t)(n * HROW + (q & 1) * 16);
        }

#pragma unroll
        for (int c = 0; c < 16; ++c) {          // 16 k16 chunks
            const uint32_t koff = (uint32_t)(c * 32);
            uint32_t af[2][4], bf[4];
#pragma unroll
            for (int i = 0; i < 2; ++i)
                ldsm4(af[i], h2b + hoffA[i] + koff);
            ldsm4(bf, whb + hoffB + koff);
#pragma unroll
            for (int i = 0; i < 2; ++i)
#pragma unroll
                for (int j = 0; j < 2; ++j)
                    mma16816(acc2[i][j], af[i], &bf[j * 2]);
        }

        // epilogue: bias + pairwise softmax + store
#pragma unroll
        for (int i = 0; i < 2; ++i) {
#pragma unroll
            for (int row = 0; row < 2; ++row) {
                const int m = wm2 * 32 + i * 16 + row * 8 + g;
                float* op = out + (posb + m) * 54;
#pragma unroll
                for (int j = 0; j < 2; ++j) {
                    const int n0 = wn2 * 16 + j * 8 + 2 * t4;
                    if (n0 < 54) {
                        float v0 = acc2[i][j][row * 2 + 0] + bh_s[n0];
                        float v1 = acc2[i][j][row * 2 + 1] + bh_s[n0 + 1];
                        const int a   = n0 / 6;
                        const int rem = n0 - 6 * a;
                        if (rem == 0) {
                            const float mx = fmaxf(v0, v1);
                            const float e0 = __expf(v0 - mx);
                            const float e1 = __expf(v1 - mx);
                            const float inv = 1.0f / (e0 + e1);
                            v0 = e0 * inv;
                            v1 = e1 * inv;
                        }
                        *(float2*)(op + n0) = make_float2(v0, v1);
                    }
                }
            }
        }
    }
}

// ---------------------------------------------------------------------------
extern "C" void kernel_launch(void* const* d_in, const int* in_sizes, int n_in,
                              void* d_out, int out_size)
{
    const float* x  = (const float*)d_in[0];
    const float* W1 = (const float*)d_in[1];
    const float* b1 = (const float*)d_in[2];
    const float* W2 = (const float*)d_in[3];
    const float* b2 = (const float*)d_in[4];
    const float* Wr = (const float*)d_in[5];
    const float* br = (const float*)d_in[6];
    const float* Wc = (const float*)d_in[7];
    const float* bc = (const float*)d_in[8];
    float* out = (float*)d_out;

    __half *x16p, *h1p, *w1tp, *w2tp, *whp;
    float *bhp;
    cudaGetSymbolAddress((void**)&x16p, g_x16);
    cudaGetSymbolAddress((void**)&h1p,  g_h1);
    cudaGetSymbolAddress((void**)&w1tp, g_w1t);
    cudaGetSymbolAddress((void**)&w2tp, g_w2t);
    cudaGetSymbolAddress((void**)&whp,  g_wh);
    cudaGetSymbolAddress((void**)&bhp,  g_bh);

    // prep (order keeps conv1 at launch index 3 -> ncu profiles it)
    const int n8 = BATCH * HDIM * WDIM * 512 / 8;
    cvt_x_kernel<<<(n8 + 255) / 256, 256>>>(x, x16p, n8);
    wtrans_kernel<<<(9 * 512 * 256 + 255) / 256, 256>>>(W1, w1tp, 9 * 512);
    wtrans_kernel<<<(9 * 256 * 256 + 255) / 256, 256>>>(W2, w2tp, 9 * 256);

    const int conv_smem = 4 * 20480 + 2048;   // 83968 B
    cudaFuncSetAttribute(conv_mma<512, false>,
                         cudaFuncAttributeMaxDynamicSharedMemorySize, conv_smem);
    cudaFuncSetAttribute(conv_mma<256, true>,
                         cudaFuncAttributeMaxDynamicSharedMemorySize, conv_smem);

    conv_mma<512, false><<<1024, 256, conv_smem>>>(x16p, w1tp, b1, h1p,
                                                   nullptr, bhp);
    whead_kernel<<<64, 256>>>(Wr, br, Wc, bc, whp, bhp);
    conv_mma<256, true><<<1024, 256, conv_smem>>>(h1p, w2tp, b2, out,
                                                  whp, bhp);
}